// round 7
// baseline (speedup 1.0000x reference)
#include <cuda_runtime.h>
#include <cstdint>
#include <math.h>

#define NB 8
#define NS 2048
#define ND 512
#define BR 64
#define BC 64
#define DC 128
#define NTH 512

#define KS_STRIDE 132   // K raw chunk stride (floats)
#define VS_STRIDE 136   // V raw chunk stride (floats): conflict-free V-as-B loads
#define PS_STRIDE 68    // P stride: conflict-free P-as-A loads
#define QSP 132         // split-buffer stride in float2 units (132%16==4 -> LDS.64 conflict-free)

// shared memory layout (in floats)
#define OFF_QS  0
#define SZ_QS   (BR*QSP*2)                // 16896 : Q chunk split (hi,lo) pairs
#define OFF_KS  (OFF_QS + SZ_QS)
#define SZ_KS   (BC*QSP*2)                // 16896 : K chunk split (hi,lo) pairs
#define SZ_KVB  (BC*VS_STRIDE)            // 8704 per raw buffer
#define OFF_KV  (OFF_KS + SZ_KS)
#define SZ_KV   (2*SZ_KVB)                // 17408 double-buffered raw K/V
#define OFF_P   (OFF_KV + SZ_KV)
#define SZ_P    (BR*PS_STRIDE)            // 4352
#define OFF_RED (OFF_P + SZ_P)
#define SZ_RED  (8*BR)                    // 512
#define SMEM_FLOATS (OFF_RED + SZ_RED)    // 56064 floats = 224256 bytes

#define N_CHUNKS ((NS/BC)*8)              // 256 per CTA

__device__ __forceinline__ uint32_t f2tf(float x) {
    uint32_t u;
    asm("cvt.rna.tf32.f32 %0, %1;" : "=r"(u) : "f"(x));
    return u;
}

__device__ __forceinline__ uint32_t fu(float x) { return __float_as_uint(x); }

__device__ __forceinline__ uint32_t ldb(const float* p) {
    return __float_as_uint(*p);
}

// split 4 floats into (hi,lo) pairs and store 8 consecutive floats (2x STS.128)
__device__ __forceinline__ void split4_store(float* dst, float4 v) {
    float h0 = __uint_as_float(f2tf(v.x));
    float h1 = __uint_as_float(f2tf(v.y));
    float h2 = __uint_as_float(f2tf(v.z));
    float h3 = __uint_as_float(f2tf(v.w));
    float4 s0 = make_float4(h0, v.x - h0, h1, v.y - h1);
    float4 s1 = make_float4(h2, v.z - h2, h3, v.w - h3);
    *reinterpret_cast<float4*>(dst)     = s0;
    *reinterpret_cast<float4*>(dst + 4) = s1;
}

__device__ __forceinline__ void mma8(float c[4],
                                     uint32_t a0, uint32_t a1, uint32_t a2, uint32_t a3,
                                     uint32_t b0, uint32_t b1) {
    asm volatile(
        "mma.sync.aligned.m16n8k8.row.col.f32.tf32.tf32.f32 "
        "{%0,%1,%2,%3},{%4,%5,%6,%7},{%8,%9},{%0,%1,%2,%3};\n"
        : "+f"(c[0]), "+f"(c[1]), "+f"(c[2]), "+f"(c[3])
        : "r"(a0), "r"(a1), "r"(a2), "r"(a3), "r"(b0), "r"(b1));
}

extern __shared__ float sm[];

// Issue async copy of flattened chunk index c (guarded), always commit a group.
__device__ __forceinline__ void issue_chunk(int c, const float* Kb, const float* Vb,
                                            float* kvbase, int tid) {
    if (c < N_CHUNKS) {
        const int kt = c >> 3;
        const int ph = (c >> 2) & 1;          // 0 = K, 1 = V
        const int dc = c & 3;
        const float* src = (ph ? Vb : Kb) + (size_t)(kt * BC) * ND + dc * DC;
        const int stride = ph ? VS_STRIDE : KS_STRIDE;
        float* dst = kvbase + (c & 1) * SZ_KVB;
        #pragma unroll
        for (int i = 0; i < (BC * DC / 4) / NTH; i++) {   // 4 iters @512 thr
            int idx = tid + i * NTH;
            int row = idx >> 5;               // 32 float4 per row
            int c4  = idx & 31;
            const float* g = src + (size_t)row * ND + c4 * 4;
            uint32_t saddr = (uint32_t)__cvta_generic_to_shared(dst + row * stride + c4 * 4);
            asm volatile("cp.async.cg.shared.global [%0], [%1], 16;\n"
                         :: "r"(saddr), "l"(g));
        }
    }
    asm volatile("cp.async.commit_group;\n");
}

__device__ __forceinline__ void wait_prev() {
    asm volatile("cp.async.wait_group 1;\n" ::: "memory");
}

__global__ void __launch_bounds__(NTH, 1)
attn_flash_tf32(const float* __restrict__ Q,
                const float* __restrict__ K,
                const float* __restrict__ V,
                float* __restrict__ O) {
    const int b   = blockIdx.y;
    const int q0  = blockIdx.x * BR;
    const int tid = threadIdx.x;
    const int wid = tid >> 5;
    const int lane = tid & 31;
    const int wm = wid & 3;          // warp row: 4 groups of 16 rows
    const int wn = wid >> 2;         // warp col: 4 groups over N
    const int g = lane >> 2;         // groupID
    const int t = lane & 3;          // threadID-in-group
    const int RM = wm * 16;

    const float* Qb = Q + ((size_t)b * NS + q0) * ND;
    const float* Kb = K + (size_t)b * NS * ND;
    const float* Vb = V + (size_t)b * NS * ND;

    float* Qs  = sm + OFF_QS;
    float* Ks  = sm + OFF_KS;
    float* KVb = sm + OFF_KV;
    float* Ps  = sm + OFF_P;
    float* red = sm + OFF_RED;

    // kick off the async pipeline
    issue_chunk(0, Kb, Vb, KVb, tid);
    issue_chunk(1, Kb, Vb, KVb, tid);

    // output accumulators: o[dc][n8][4]
    float o[4][4][4];
    #pragma unroll
    for (int a = 0; a < 4; a++)
        #pragma unroll
        for (int n = 0; n < 4; n++)
            #pragma unroll
            for (int c = 0; c < 4; c++) o[a][n][c] = 0.f;

    float m_r[2] = {-INFINITY, -INFINITY};
    float l_r[2] = {0.f, 0.f};

    for (int kt = 0; kt < NS / BC; kt++) {
        // ---- S = Q K^T (64x64), 4 async-pipelined D-chunks, 3xTF32 via split buffers ----
        float sc[2][4];
        #pragma unroll
        for (int n = 0; n < 2; n++)
            #pragma unroll
            for (int c = 0; c < 4; c++) sc[n][c] = 0.f;

        for (int dc = 0; dc < ND / DC; dc++) {
            const int cc = kt * 8 + dc;

            // prefetch Q chunk from global (L2-resident) while cp.async drains
            float4 qv[4];
            #pragma unroll
            for (int i = 0; i < 4; i++) {
                int idx = tid + i * NTH;
                int row = idx >> 5, c4 = idx & 31;
                qv[i] = *reinterpret_cast<const float4*>(
                    Qb + (size_t)row * ND + dc * DC + c4 * 4);
            }

            wait_prev();
            __syncthreads();
            const float* Kraw = KVb + (cc & 1) * SZ_KVB;

            // cooperative split: each element split exactly once per chunk
            #pragma unroll
            for (int i = 0; i < 4; i++) {
                int idx = tid + i * NTH;
                int row = idx >> 5, c4 = idx & 31;
                float4 kv4 = *reinterpret_cast<const float4*>(Kraw + row * KS_STRIDE + c4 * 4);
                split4_store(Ks + (row * QSP + c4 * 4) * 2, kv4);
                split4_store(Qs + (row * QSP + c4 * 4) * 2, qv[i]);
            }
            __syncthreads();
            issue_chunk(cc + 2, Kb, Vb, KVb, tid);   // raw buffer drained; overlap with MMA

            #pragma unroll
            for (int kk = 0; kk < DC; kk += 8) {
                const float* q0p = Qs + ((RM + g) * QSP + kk + t) * 2;
                const float* q1p = Qs + ((RM + g + 8) * QSP + kk + t) * 2;
                float2 qa0 = *reinterpret_cast<const float2*>(q0p);
                float2 qa1 = *reinterpret_cast<const float2*>(q1p);
                float2 qa2 = *reinterpret_cast<const float2*>(q0p + 8);
                float2 qa3 = *reinterpret_cast<const float2*>(q1p + 8);
                #pragma unroll
                for (int n8 = 0; n8 < 2; n8++) {
                    int col = wn * 16 + n8 * 8 + g;
                    const float* kp = Ks + (col * QSP + kk + t) * 2;
                    float2 kb0 = *reinterpret_cast<const float2*>(kp);
                    float2 kb1 = *reinterpret_cast<const float2*>(kp + 8);
                    // 3xTF32: hi*hi + lo*hi + hi*lo
                    mma8(sc[n8], fu(qa0.x), fu(qa1.x), fu(qa2.x), fu(qa3.x), fu(kb0.x), fu(kb1.x));
                    mma8(sc[n8], fu(qa0.y), fu(qa1.y), fu(qa2.y), fu(qa3.y), fu(kb0.x), fu(kb1.x));
                    mma8(sc[n8], fu(qa0.x), fu(qa1.x), fu(qa2.x), fu(qa3.x), fu(kb0.y), fu(kb1.y));
                }
            }
        }

        // ---- online softmax: row max (4-way cross-warp over wn) ----
        #pragma unroll
        for (int j = 0; j < 2; j++) {
            float mx = fmaxf(sc[0][2 * j], sc[0][2 * j + 1]);
            mx = fmaxf(mx, fmaxf(sc[1][2 * j], sc[1][2 * j + 1]));
            mx = fmaxf(mx, __shfl_xor_sync(0xffffffffu, mx, 1));
            mx = fmaxf(mx, __shfl_xor_sync(0xffffffffu, mx, 2));
            if (t == 0) red[wn * BR + RM + g + 8 * j] = mx;
        }
        __syncthreads();

        float scale[2];
        #pragma unroll
        for (int j = 0; j < 2; j++) {
            int row = RM + g + 8 * j;
            float mt = fmaxf(fmaxf(red[row], red[BR + row]),
                             fmaxf(red[2 * BR + row], red[3 * BR + row]));
            float mnew = fmaxf(m_r[j], mt);
            scale[j] = __expf(m_r[j] - mnew);
            m_r[j] = mnew;
        }

        // ---- exponentiate, row-sum over the ROUNDED values, write P (tf32) ----
        float lsum_loc[2] = {0.f, 0.f};
        #pragma unroll
        for (int n8 = 0; n8 < 2; n8++) {
            #pragma unroll
            for (int j = 0; j < 2; j++) {
                float p0 = __expf(sc[n8][2 * j]     - m_r[j]);
                float p1 = __expf(sc[n8][2 * j + 1] - m_r[j]);
                uint32_t u0 = f2tf(p0), u1 = f2tf(p1);
                lsum_loc[j] += __uint_as_float(u0) + __uint_as_float(u1);
                int row = RM + g + 8 * j;
                int col = wn * 16 + n8 * 8 + 2 * t;
                *reinterpret_cast<uint2*>(Ps + row * PS_STRIDE + col) = make_uint2(u0, u1);
            }
        }
        #pragma unroll
        for (int j = 0; j < 2; j++) {
            lsum_loc[j] += __shfl_xor_sync(0xffffffffu, lsum_loc[j], 1);
            lsum_loc[j] += __shfl_xor_sync(0xffffffffu, lsum_loc[j], 2);
            if (t == 0) red[4 * BR + wn * BR + RM + g + 8 * j] = lsum_loc[j];
        }
        __syncthreads();   // Ps + sum partials visible

        #pragma unroll
        for (int j = 0; j < 2; j++) {
            int row = RM + g + 8 * j;
            float ls = (red[4 * BR + row] + red[5 * BR + row]) +
                       (red[6 * BR + row] + red[7 * BR + row]);
            l_r[j] = l_r[j] * scale[j] + ls;
        }

        // rescale existing O accumulators
        #pragma unroll
        for (int a = 0; a < 4; a++)
            #pragma unroll
            for (int n = 0; n < 4; n++) {
                o[a][n][0] *= scale[0];
                o[a][n][1] *= scale[0];
                o[a][n][2] *= scale[1];
                o[a][n][3] *= scale[1];
            }

        // ---- O += P V, async-pipelined V chunks (V fed raw; HW tf32 truncation) ----
        for (int dc = 0; dc < ND / DC; dc++) {
            const int cc = kt * 8 + 4 + dc;
            wait_prev();
            __syncthreads();
            const float* Vc = KVb + (cc & 1) * SZ_KVB;

            #pragma unroll
            for (int kk = 0; kk < BC; kk += 8) {
                const float* prow0 = Ps + (RM + g) * PS_STRIDE + kk + t;
                const float* prow1 = Ps + (RM + g + 8) * PS_STRIDE + kk + t;
                uint32_t a0 = ldb(prow0);
                uint32_t a1 = ldb(prow1);
                uint32_t a2 = ldb(prow0 + 4);
                uint32_t a3 = ldb(prow1 + 4);
                #pragma unroll
                for (int n8 = 0; n8 < 4; n8++) {
                    int col = wn * 32 + n8 * 8 + g;
                    uint32_t b0 = ldb(Vc + (kk + t) * VS_STRIDE + col);
                    uint32_t b1 = ldb(Vc + (kk + t + 4) * VS_STRIDE + col);
                    mma8(o[dc][n8], a0, a1, a2, a3, b0, b1);
                }
            }
            __syncthreads();
            issue_chunk(cc + 2, Kb, Vb, KVb, tid);
        }
    }

    // ---- normalize and write output ----
    float inv[2] = {1.f / l_r[0], 1.f / l_r[1]};
    float* Ob = O + ((size_t)b * NS + q0) * ND;
    #pragma unroll
    for (int dc = 0; dc < 4; dc++)
        #pragma unroll
        for (int n8 = 0; n8 < 4; n8++)
            #pragma unroll
            for (int j = 0; j < 2; j++) {
                int row = RM + g + 8 * j;
                int col = dc * DC + wn * 32 + n8 * 8 + 2 * t;
                float2 v = make_float2(o[dc][n8][2 * j] * inv[j],
                                       o[dc][n8][2 * j + 1] * inv[j]);
                *reinterpret_cast<float2*>(Ob + (size_t)row * ND + col) = v;
            }
}

extern "C" void kernel_launch(void* const* d_in, const int* in_sizes, int n_in,
                              void* d_out, int out_size) {
    const float* q = (const float*)d_in[0];
    const float* k = (const float*)d_in[1];
    const float* v = (const float*)d_in[2];
    float* o = (float*)d_out;

    const int smem_bytes = SMEM_FLOATS * 4;   // 224256
    cudaFuncSetAttribute(attn_flash_tf32,
                         cudaFuncAttributeMaxDynamicSharedMemorySize, smem_bytes);
    dim3 grid(NS / BR, NB);
    attn_flash_tf32<<<grid, NTH, smem_bytes>>>(q, k, v, o);
}

// round 9
// speedup vs baseline: 2.2381x; 2.2381x over previous
#include <cuda_runtime.h>
#include <cuda_fp16.h>
#include <cstdint>
#include <math.h>

#define NB 8
#define NS 2048
#define ND 512
#define BR 64
#define BC 64
#define DCK 128          // QK contraction chunk (k elems)
#define DVC 128          // PV d-output chunk
#define NTH 512

// ---- device scratch: pre-split f16 planes + transposed V ----
__device__ __half g_Qhi[NB * NS * ND];
__device__ __half g_Qlo[NB * NS * ND];
__device__ __half g_Khi[NB * NS * ND];
__device__ __half g_Klo[NB * NS * ND];
__device__ __half g_Vt [NB * ND * NS];   // [b][d][s]

// ---- smem layout in 32-bit words (each word = f16x2 along the k/s dim) ----
#define QW 260                       // Q plane row stride (256 data words + 4 pad; 260%32==4)
#define OFF_QH 0                     // Q hi plane: 64 x QW
#define OFF_QL (64 * QW)             // 16640 : Q lo plane
#define OFF_KV (2 * 64 * QW)         // 33280 : double-buffered K/V chunk region
#define KVSLOT 8704                  // words per buffer slot
#define KW 68                        // K chunk row stride (64 data + 4 pad)
#define VW 36                        // Vt chunk row stride (32 data + 4 pad)
#define OFF_P (OFF_KV + 2 * KVSLOT)  // 50688 : P tile (f16x2)
#define PW 36                        // P row stride
#define OFF_RED (OFF_P + 64 * PW)    // 52992 : reduction scratch (floats)
#define SMEM_WORDS (OFF_RED + 8 * 64)  // 53504 words = 214016 bytes

#define N_CHUNKS ((NS / BC) * 8)     // 32 tiles * (4 K-events + 4 V-events) = 256

__device__ __forceinline__ uint32_t pack2(float a, float b) {
    __half2 h = __floats2half2_rn(a, b);
    return *reinterpret_cast<uint32_t*>(&h);
}

__device__ __forceinline__ void mma16(float c[4],
                                      uint32_t a0, uint32_t a1, uint32_t a2, uint32_t a3,
                                      uint32_t b0, uint32_t b1) {
    asm volatile(
        "mma.sync.aligned.m16n8k16.row.col.f32.f16.f16.f32 "
        "{%0,%1,%2,%3},{%4,%5,%6,%7},{%8,%9},{%0,%1,%2,%3};\n"
        : "+f"(c[0]), "+f"(c[1]), "+f"(c[2]), "+f"(c[3])
        : "r"(a0), "r"(a1), "r"(a2), "r"(a3), "r"(b0), "r"(b1));
}

// ============ prologue kernels ============

// split fp32 -> (hi, lo) f16 planes.
__global__ void __launch_bounds__(512) split_f16_kernel(const float* __restrict__ x, int isK) {
    __half* __restrict__ hi = isK ? g_Khi : g_Qhi;
    __half* __restrict__ lo = isK ? g_Klo : g_Qlo;
    int i = blockIdx.x * 512 + threadIdx.x;
    float4 v = reinterpret_cast<const float4*>(x)[i];
    __half h0 = __float2half_rn(v.x);
    __half h1 = __float2half_rn(v.y);
    __half h2 = __float2half_rn(v.z);
    __half h3 = __float2half_rn(v.w);
    __half l0 = __float2half_rn(v.x - __half2float(h0));
    __half l1 = __float2half_rn(v.y - __half2float(h1));
    __half l2 = __float2half_rn(v.z - __half2float(h2));
    __half l3 = __float2half_rn(v.w - __half2float(h3));
    __half2* hp = reinterpret_cast<__half2*>(hi) + 2 * i;
    __half2* lp = reinterpret_cast<__half2*>(lo) + 2 * i;
    hp[0] = __halves2half2(h0, h1);
    hp[1] = __halves2half2(h2, h3);
    lp[0] = __halves2half2(l0, l1);
    lp[1] = __halves2half2(l2, l3);
}

// V [b][s][d] fp32 -> g_Vt [b][d][s] f16, 64x64 tiles through smem.
__global__ void __launch_bounds__(256) vtrans_kernel(const float* __restrict__ V) {
    __shared__ __half tile[64 * 66];
    int b = blockIdx.z, s0 = blockIdx.x * 64, d0 = blockIdx.y * 64;
    int tid = threadIdx.x;
    #pragma unroll
    for (int i = 0; i < 16; i++) {
        int idx = tid + i * 256;
        int r = idx >> 6, c = idx & 63;
        float x = V[((size_t)b * NS + s0 + r) * ND + d0 + c];
        tile[c * 66 + r] = __float2half_rn(x);
    }
    __syncthreads();
    #pragma unroll
    for (int i = 0; i < 16; i++) {
        int idx = tid + i * 256;
        int r = idx >> 6, c = idx & 63;
        g_Vt[((size_t)b * ND + d0 + r) * NS + s0 + c] = tile[r * 66 + c];
    }
}

// ============ main kernel ============

extern __shared__ uint32_t smw[];

// flattened chunk event c: tile kt = c>>3; c&4 ? V-event : K-event; dc = c&3.
// K-event: Khi+Klo chunks (2 planes x 64 rows x 256B = 2048 x 16B ops).
// V-event: Vt chunk (128 d-rows x 128B = 1024 x 16B ops).
__device__ __forceinline__ void issue_chunk(int c, int b, int tid) {
    if (c < N_CHUNKS) {
        const int kt = c >> 3;
        const int dc = c & 3;
        uint32_t* dst = smw + OFF_KV + (c & 1) * KVSLOT;
        if (!(c & 4)) {
            // K event: 2048 ops of 16B (full 64-word rows, both planes)
            #pragma unroll
            for (int i = 0; i < 4; i++) {
                int idx = tid + i * NTH;
                int plane = idx >> 10;
                int r = (idx >> 4) & 63;
                int j = idx & 15;                 // 16B unit within 256B row
                const __half* src = (plane ? g_Klo : g_Khi) +
                    ((size_t)(b * NS + kt * BC + r)) * ND + dc * DCK + j * 8;
                uint32_t saddr = (uint32_t)__cvta_generic_to_shared(
                    dst + plane * (64 * KW) + r * KW + j * 4);
                asm volatile("cp.async.cg.shared.global [%0], [%1], 16;\n"
                             :: "r"(saddr), "l"(src));
            }
        } else {
            // V event: 128 d-rows x 8 ops(16B) = 1024 ops
            #pragma unroll
            for (int i = 0; i < 2; i++) {
                int idx = tid + i * NTH;
                int r = idx >> 3;
                int j = idx & 7;
                const __half* src = g_Vt +
                    ((size_t)(b * ND) + dc * DVC + r) * NS + kt * BC + j * 8;
                uint32_t saddr = (uint32_t)__cvta_generic_to_shared(dst + r * VW + j * 4);
                asm volatile("cp.async.cg.shared.global [%0], [%1], 16;\n"
                             :: "r"(saddr), "l"(src));
            }
        }
    }
    asm volatile("cp.async.commit_group;\n");
}

__device__ __forceinline__ void wait_prev() {
    asm volatile("cp.async.wait_group 1;\n" ::: "memory");
}

__global__ void __launch_bounds__(NTH, 1)
attn_flash_f16x3(const float* __restrict__ O_unused, float* __restrict__ O) {
    const int b   = blockIdx.y;
    const int q0  = blockIdx.x * BR;
    const int tid = threadIdx.x;
    const int wid = tid >> 5;
    const int lane = tid & 31;
    const int wm = wid & 3;          // warp row: 4 groups of 16 rows
    const int wn = wid >> 2;         // warp col: 4 groups over N
    const int g = lane >> 2;
    const int t = lane & 3;
    const int RM = wm * 16;

    float* red = reinterpret_cast<float*>(smw + OFF_RED);

    // kick off async pipeline
    issue_chunk(0, b, tid);
    issue_chunk(1, b, tid);

    // ---- load persistent Q hi/lo tiles (64 x 512 f16 each) ----
    #pragma unroll
    for (int i = 0; i < 8; i++) {
        int idx = tid + i * NTH;
        int r = idx >> 6, j = idx & 63;          // j: 16B unit within row
        const size_t goff = ((size_t)(b * NS + q0 + r)) * ND + j * 8;
        uint4 vh = *reinterpret_cast<const uint4*>(g_Qhi + goff);
        uint4 vl = *reinterpret_cast<const uint4*>(g_Qlo + goff);
        *reinterpret_cast<uint4*>(smw + OFF_QH + r * QW + j * 4) = vh;
        *reinterpret_cast<uint4*>(smw + OFF_QL + r * QW + j * 4) = vl;
    }

    float o[4][4][4];
    #pragma unroll
    for (int a = 0; a < 4; a++)
        #pragma unroll
        for (int n = 0; n < 4; n++)
            #pragma unroll
            for (int c = 0; c < 4; c++) o[a][n][c] = 0.f;

    float m_r[2] = {-INFINITY, -INFINITY};
    float l_r[2] = {0.f, 0.f};

    const uint32_t* QH = smw + OFF_QH;
    const uint32_t* QL = smw + OFF_QL;
    uint32_t* PS = smw + OFF_P;
    const int rowA = (RM + g) * QW;
    const int rowB = (RM + g + 8) * QW;

    for (int kt = 0; kt < NS / BC; kt++) {
        // ---- S = Q K^T, 3xF16 (hi*hi + lo*hi + hi*lo), 4 pipelined k-chunks ----
        float sc[2][4];
        #pragma unroll
        for (int n = 0; n < 2; n++)
            #pragma unroll
            for (int c = 0; c < 4; c++) sc[n][c] = 0.f;

        for (int dc = 0; dc < 4; dc++) {
            const int cc = kt * 8 + dc;
            wait_prev();
            __syncthreads();
            const uint32_t* Kc = smw + OFF_KV + (cc & 1) * KVSLOT;
            const uint32_t* Kl = Kc + 64 * KW;

            #pragma unroll
            for (int kk = 0; kk < 8; kk++) {         // 16 k per step
                const int wq = dc * 64 + kk * 8 + t;
                uint32_t ah0 = QH[rowA + wq], ah1 = QH[rowB + wq];
                uint32_t ah2 = QH[rowA + wq + 4], ah3 = QH[rowB + wq + 4];
                uint32_t al0 = QL[rowA + wq], al1 = QL[rowB + wq];
                uint32_t al2 = QL[rowA + wq + 4], al3 = QL[rowB + wq + 4];
                #pragma unroll
                for (int n8 = 0; n8 < 2; n8++) {
                    const int col = wn * 16 + n8 * 8 + g;
                    const int kb = col * KW + kk * 8 + t;
                    uint32_t kh0 = Kc[kb], kh1 = Kc[kb + 4];
                    uint32_t kl0 = Kl[kb], kl1 = Kl[kb + 4];
                    mma16(sc[n8], ah0, ah1, ah2, ah3, kh0, kh1);
                    mma16(sc[n8], al0, al1, al2, al3, kh0, kh1);
                    mma16(sc[n8], ah0, ah1, ah2, ah3, kl0, kl1);
                }
            }
            __syncthreads();
            issue_chunk(cc + 2, b, tid);
        }

        // ---- online softmax: row max (4-way cross-warp over wn) ----
        #pragma unroll
        for (int j = 0; j < 2; j++) {
            float mx = fmaxf(sc[0][2 * j], sc[0][2 * j + 1]);
            mx = fmaxf(mx, fmaxf(sc[1][2 * j], sc[1][2 * j + 1]));
            mx = fmaxf(mx, __shfl_xor_sync(0xffffffffu, mx, 1));
            mx = fmaxf(mx, __shfl_xor_sync(0xffffffffu, mx, 2));
            if (t == 0) red[wn * BR + RM + g + 8 * j] = mx;
        }
        __syncthreads();

        float scale[2];
        #pragma unroll
        for (int j = 0; j < 2; j++) {
            int row = RM + g + 8 * j;
            float mt = fmaxf(fmaxf(red[row], red[BR + row]),
                             fmaxf(red[2 * BR + row], red[3 * BR + row]));
            float mnew = fmaxf(m_r[j], mt);
            scale[j] = __expf(m_r[j] - mnew);
            m_r[j] = mnew;
        }

        // ---- exponentiate, row-sum over ROUNDED f16 values, write P ----
        float lsum_loc[2] = {0.f, 0.f};
        #pragma unroll
        for (int n8 = 0; n8 < 2; n8++) {
            #pragma unroll
            for (int j = 0; j < 2; j++) {
                float p0 = __expf(sc[n8][2 * j]     - m_r[j]);
                float p1 = __expf(sc[n8][2 * j + 1] - m_r[j]);
                uint32_t w = pack2(p0, p1);
                __half2 h = *reinterpret_cast<__half2*>(&w);
                float2 pf = __half22float2(h);
                lsum_loc[j] += pf.x + pf.y;
                int row = RM + g + 8 * j;
                PS[row * PW + wn * 8 + n8 * 4 + t] = w;
            }
        }
        #pragma unroll
        for (int j = 0; j < 2; j++) {
            lsum_loc[j] += __shfl_xor_sync(0xffffffffu, lsum_loc[j], 1);
            lsum_loc[j] += __shfl_xor_sync(0xffffffffu, lsum_loc[j], 2);
            if (t == 0) red[4 * BR + wn * BR + RM + g + 8 * j] = lsum_loc[j];
        }
        __syncthreads();   // P + sum partials visible

        #pragma unroll
        for (int j = 0; j < 2; j++) {
            int row = RM + g + 8 * j;
            float ls = (red[4 * BR + row] + red[5 * BR + row]) +
                       (red[6 * BR + row] + red[7 * BR + row]);
            l_r[j] = l_r[j] * scale[j] + ls;
        }

        // rescale O accumulators
        #pragma unroll
        for (int a = 0; a < 4; a++)
            #pragma unroll
            for (int n = 0; n < 4; n++) {
                o[a][n][0] *= scale[0];
                o[a][n][1] *= scale[0];
                o[a][n][2] *= scale[1];
                o[a][n][3] *= scale[1];
            }

        // ---- O += P V : f16 MMA over transposed-V chunks ----
        for (int dc = 0; dc < 4; dc++) {
            const int cc = kt * 8 + 4 + dc;
            wait_prev();
            __syncthreads();
            const uint32_t* Vc = smw + OFF_KV + (cc & 1) * KVSLOT;

            #pragma unroll
            for (int kk = 0; kk < 4; kk++) {         // 16 kv per step
                const int kwv = kk * 8 + t;
                uint32_t a0 = PS[(RM + g) * PW + kwv];
                uint32_t a1 = PS[(RM + g + 8) * PW + kwv];
                uint32_t a2 = PS[(RM + g) * PW + kwv + 4];
                uint32_t a3 = PS[(RM + g + 8) * PW + kwv + 4];
                #pragma unroll
                for (int n8 = 0; n8 < 4; n8++) {
                    const int dcol = wn * 32 + n8 * 8 + g;
                    uint32_t b0 = Vc[dcol * VW + kwv];
                    uint32_t b1 = Vc[dcol * VW + kwv + 4];
                    mma16(o[dc][n8], a0, a1, a2, a3, b0, b1);
                }
            }
            __syncthreads();
            issue_chunk(cc + 2, b, tid);
        }
    }

    // ---- normalize and write output ----
    float inv[2] = {1.f / l_r[0], 1.f / l_r[1]};
    float* Ob = O + ((size_t)b * NS + q0) * ND;
    #pragma unroll
    for (int dc = 0; dc < 4; dc++)
        #pragma unroll
        for (int n8 = 0; n8 < 4; n8++)
            #pragma unroll
            for (int j = 0; j < 2; j++) {
                int row = RM + g + 8 * j;
                int col = dc * DVC + wn * 32 + n8 * 8 + 2 * t;
                float2 v = make_float2(o[dc][n8][2 * j] * inv[j],
                                       o[dc][n8][2 * j + 1] * inv[j]);
                *reinterpret_cast<float2*>(Ob + (size_t)row * ND + col) = v;
            }
}

extern "C" void kernel_launch(void* const* d_in, const int* in_sizes, int n_in,
                              void* d_out, int out_size) {
    const float* q = (const float*)d_in[0];
    const float* k = (const float*)d_in[1];
    const float* v = (const float*)d_in[2];
    float* o = (float*)d_out;

    // prologue: split Q/K into f16 hi/lo planes, transpose V to f16 [b][d][s]
    split_f16_kernel<<<4096, 512>>>(q, 0);
    split_f16_kernel<<<4096, 512>>>(k, 1);
    dim3 tg(NS / 64, ND / 64, NB);
    vtrans_kernel<<<tg, 256>>>(v);

    const int smem_bytes = SMEM_WORDS * 4;   // 214016
    cudaFuncSetAttribute(attn_flash_f16x3,
                         cudaFuncAttributeMaxDynamicSharedMemorySize, smem_bytes);
    dim3 grid(NS / BR, NB);
    attn_flash_f16x3<<<grid, NTH, smem_bytes>>>(q, o);
}